// round 1
// baseline (speedup 1.0000x reference)
#include <cuda_runtime.h>
#include <math.h>

#define N 8192
#define D 256
#define H 64

#define RT 64          // rows per block
#define CT 128         // cols per tile
#define KT 32          // k per chunk
#define NT 256         // threads per block
#define APAD 65        // A tile stride (conflict-free)
#define BPAD 129       // B tile stride (conflict-free)

#define MARGIN 100.0f
#define GAMMA 2.0f

__device__ float g_pn[N * D];     // pred_norm
__device__ float g_tn[N * D];     // target_norm
__device__ float g_terms[N];      // per-row loss terms

// ---------------------------------------------------------------------------
// Kernel 1: pred = relu(x @ W1 + b1) @ W2 + b2, then L2-normalize row.
// One block per row, 256 threads.
// ---------------------------------------------------------------------------
__global__ void pred_norm_kernel(const float* __restrict__ x,
                                 const float* __restrict__ W1,
                                 const float* __restrict__ b1,
                                 const float* __restrict__ W2,
                                 const float* __restrict__ b2) {
    __shared__ float xs[D];
    __shared__ float hs[H];
    __shared__ float red[NT];

    const int row = blockIdx.x;
    const int t = threadIdx.x;

    xs[t] = x[row * D + t];
    __syncthreads();

    if (t < H) {
        float acc = b1[t];
#pragma unroll 8
        for (int k = 0; k < D; k++) acc = fmaf(xs[k], W1[k * H + t], acc);
        hs[t] = fmaxf(acc, 0.0f);
    }
    __syncthreads();

    float p = b2[t];
#pragma unroll 8
    for (int j = 0; j < H; j++) p = fmaf(hs[j], W2[j * D + t], p);

    red[t] = p * p;
    __syncthreads();
#pragma unroll
    for (int s = NT / 2; s > 0; s >>= 1) {
        if (t < s) red[t] += red[t + s];
        __syncthreads();
    }
    const float inv = 1.0f / fmaxf(sqrtf(red[0]), 1e-12f);
    g_pn[row * D + t] = p * inv;
}

// ---------------------------------------------------------------------------
// Kernel 2: L2-normalize target rows. One block per row.
// ---------------------------------------------------------------------------
__global__ void target_norm_kernel(const float* __restrict__ tgt) {
    __shared__ float red[NT];
    const int row = blockIdx.x;
    const int t = threadIdx.x;

    const float v = tgt[row * D + t];
    red[t] = v * v;
    __syncthreads();
#pragma unroll
    for (int s = NT / 2; s > 0; s >>= 1) {
        if (t < s) red[t] += red[t + s];
        __syncthreads();
    }
    const float inv = 1.0f / fmaxf(sqrtf(red[0]), 1e-12f);
    g_tn[row * D + t] = v * inv;
}

// ---------------------------------------------------------------------------
// Kernel 3: fused dot-product GEMM + per-row top-10 largest dot selection.
// Block = 64 rows, streams 128-col tiles over all 8192 targets.
// dist[i,j] = -2*dot  =>  smallest-10 dist == largest-10 dot.
// Reference drops smallest dist (largest dot) and averages ranks 1..9.
// ---------------------------------------------------------------------------
__global__ __launch_bounds__(NT) void dist_topk_kernel() {
    // union: {A tile + B tile} during GEMM, C tile during scan
    __shared__ float smem[RT * CT];          // 8192 floats = 32 KB
    float* As = smem;                        // KT*APAD = 2080 floats
    float* Bs = smem + KT * APAD;            // KT*BPAD = 4128 floats (tot 6208 < 8192)
    float* Cs = smem;                        // RT*CT  = 8192 floats

    const int tid = threadIdx.x;
    const int tx = tid & 31;                 // 0..31
    const int ty = tid >> 5;                 // 0..7
    const int row0 = blockIdx.x * RT;

    float top[10];                           // descending, largest dot first
#pragma unroll
    for (int q = 0; q < 10; q++) top[q] = -1e30f;
    float diag = 0.0f;

    for (int c0 = 0; c0 < N; c0 += CT) {
        float acc[8][4];
#pragma unroll
        for (int rr = 0; rr < 8; rr++)
#pragma unroll
            for (int cc = 0; cc < 4; cc++) acc[rr][cc] = 0.0f;

        for (int k0 = 0; k0 < D; k0 += KT) {
            __syncthreads();  // smem free (prev scan / prev chunk done)
            // load A tile: 64 rows x 32 k  (coalesced gmem, conflict-free smem)
            for (int idx = tid; idx < RT * KT; idx += NT) {
                const int r = idx >> 5, k = idx & 31;
                As[k * APAD + r] = g_pn[(row0 + r) * D + k0 + k];
            }
            // load B tile: 128 cols x 32 k
            for (int idx = tid; idx < CT * KT; idx += NT) {
                const int c = idx >> 5, k = idx & 31;
                Bs[k * BPAD + c] = g_tn[(c0 + c) * D + k0 + k];
            }
            __syncthreads();

#pragma unroll
            for (int k = 0; k < KT; k++) {
                float a[8], b[4];
#pragma unroll
                for (int rr = 0; rr < 8; rr++) a[rr] = As[k * APAD + ty * 8 + rr];
#pragma unroll
                for (int cc = 0; cc < 4; cc++) b[cc] = Bs[k * BPAD + tx + cc * 32];
#pragma unroll
                for (int rr = 0; rr < 8; rr++)
#pragma unroll
                    for (int cc = 0; cc < 4; cc++)
                        acc[rr][cc] = fmaf(a[rr], b[cc], acc[rr][cc]);
            }
        }
        __syncthreads();
        // write C tile to smem (conflict-free: consecutive tx -> consecutive col)
#pragma unroll
        for (int rr = 0; rr < 8; rr++)
#pragma unroll
            for (int cc = 0; cc < 4; cc++)
                Cs[(ty * 8 + rr) * CT + tx + cc * 32] = acc[rr][cc];
        __syncthreads();

        // scan phase: threads 0..63 each own one row, staggered start
        if (tid < RT) {
            const int i = row0 + tid;
            for (int t2 = 0; t2 < CT; t2++) {
                const int c = (tid + t2) & (CT - 1);   // bank-stagger
                const float v = Cs[tid * CT + c];
                const int j = c0 + c;
                if (j == i) {
                    diag = v;
                } else if (v > top[9]) {
                    // static-index bubble insert: keeps top[] in registers
                    top[9] = v;
#pragma unroll
                    for (int p = 9; p > 0; p--) {
                        if (top[p] > top[p - 1]) {
                            const float tmp = top[p - 1];
                            top[p - 1] = top[p];
                            top[p] = tmp;
                        }
                    }
                }
            }
        }
        // next iteration's leading __syncthreads() protects Cs from overwrite
    }

    if (tid < RT) {
        float s9 = 0.0f;
#pragma unroll
        for (int q = 1; q < 10; q++) s9 += top[q];
        const float dist_an = (-2.0f / 9.0f) * s9;
        const float dist_ap = -2.0f * diag;
        g_terms[row0 + tid] = fmaxf(0.0f, GAMMA * dist_ap - dist_an + MARGIN);
    }
}

// ---------------------------------------------------------------------------
// Kernel 4: deterministic fixed-order mean reduction.
// ---------------------------------------------------------------------------
__global__ void reduce_kernel(float* __restrict__ out) {
    __shared__ float red[NT];
    const int t = threadIdx.x;
    float s = 0.0f;
    for (int i = t; i < N; i += NT) s += g_terms[i];
    red[t] = s;
    __syncthreads();
#pragma unroll
    for (int sft = NT / 2; sft > 0; sft >>= 1) {
        if (t < sft) red[t] += red[t + sft];
        __syncthreads();
    }
    if (t == 0) out[0] = red[0] / (float)N;
}

// ---------------------------------------------------------------------------
extern "C" void kernel_launch(void* const* d_in, const int* in_sizes, int n_in,
                              void* d_out, int out_size) {
    const float* input  = (const float*)d_in[0];
    const float* target = (const float*)d_in[1];
    const float* W1     = (const float*)d_in[2];
    const float* b1     = (const float*)d_in[3];
    const float* W2     = (const float*)d_in[4];
    const float* b2     = (const float*)d_in[5];
    float* out = (float*)d_out;

    pred_norm_kernel<<<N, NT>>>(input, W1, b1, W2, b2);
    target_norm_kernel<<<N, NT>>>(target);
    dist_topk_kernel<<<N / RT, NT>>>();
    reduce_kernel<<<1, NT>>>(out);
}

// round 10
// speedup vs baseline: 8.3140x; 8.3140x over previous
#include <cuda_runtime.h>
#include <cuda_bf16.h>
#include <cstdint>
#include <math.h>

#define N 8192
#define D 256
#define H 64
#define MARGIN 100.0f
#define GAMMA 2.0f

// ---------------------------------------------------------------------------
// Device scratch (no allocs allowed)
// ---------------------------------------------------------------------------
__device__ float          g_tn32[N * D];      // target_norm fp32 (for exact diag)
__device__ __nv_bfloat16  g_tnb[N * D];       // target_norm bf16 (GEMM B)
__device__ __nv_bfloat16  g_pnb[N * D];       // pred_norm bf16 (GEMM A)
__device__ float          g_diag[N];          // exact <pred_norm_i, target_norm_i>
__device__ float          g_part[2 * N * 10]; // per-half top-10 dots (descending)
__device__ float          g_terms[N];         // per-row loss terms

// ---------------------------------------------------------------------------
// PTX helpers — base-target instructions ONLY (sm_103 PTX target, no 'a')
// ---------------------------------------------------------------------------
__device__ __forceinline__ uint32_t smem_u32(const void* p) {
    uint32_t a;
    asm("{ .reg .u64 t; cvta.to.shared.u64 t, %1; cvt.u32.u64 %0, t; }"
        : "=r"(a) : "l"(p));
    return a;
}

__device__ __forceinline__ void ldmatrix_x4(uint32_t& r0, uint32_t& r1,
                                            uint32_t& r2, uint32_t& r3,
                                            uint32_t addr) {
    asm volatile("ldmatrix.sync.aligned.m8n8.x4.shared.b16 {%0,%1,%2,%3}, [%4];"
                 : "=r"(r0), "=r"(r1), "=r"(r2), "=r"(r3) : "r"(addr));
}

__device__ __forceinline__ void mma_bf16(float* d, const uint32_t* a, const uint32_t* b) {
    asm volatile(
        "mma.sync.aligned.m16n8k16.row.col.f32.bf16.bf16.f32 "
        "{%0,%1,%2,%3}, {%4,%5,%6,%7}, {%8,%9}, {%0,%1,%2,%3};"
        : "+f"(d[0]), "+f"(d[1]), "+f"(d[2]), "+f"(d[3])
        : "r"(a[0]), "r"(a[1]), "r"(a[2]), "r"(a[3]), "r"(b[0]), "r"(b[1]));
}

// ---------------------------------------------------------------------------
// Kernel 1: L2-normalize target rows. 8192 blocks x 256 threads.
// ---------------------------------------------------------------------------
__global__ void target_norm_kernel(const float* __restrict__ tgt) {
    __shared__ float red[256];
    const int row = blockIdx.x;
    const int t = threadIdx.x;
    const float v = tgt[row * D + t];
    red[t] = v * v;
    __syncthreads();
#pragma unroll
    for (int s = 128; s > 0; s >>= 1) {
        if (t < s) red[t] += red[t + s];
        __syncthreads();
    }
    const float inv = 1.0f / fmaxf(sqrtf(red[0]), 1e-12f);
    const float vn = v * inv;
    g_tn32[row * D + t] = vn;
    g_tnb[row * D + t] = __float2bfloat16(vn);
}

// ---------------------------------------------------------------------------
// Kernel 2: batched MLP + normalize + exact diag dot.
// 32 rows/block, 256 threads, weights staged in SMEM (168 KB dynamic).
// ---------------------------------------------------------------------------
#define MR 32
__global__ __launch_bounds__(256) void mlp_kernel(const float* __restrict__ x,
                                                  const float* __restrict__ W1,
                                                  const float* __restrict__ b1,
                                                  const float* __restrict__ W2,
                                                  const float* __restrict__ b2) {
    extern __shared__ float fsm[];
    float* W1s = fsm;                 // [256][64]  16384 floats
    float* W2s = fsm + 16384;         // [64][256]  16384 floats
    float* xs  = fsm + 32768;         // [32][256]  8192 floats
    float* hs  = fsm + 40960;         // [32][64]   2048 floats
    float* ss  = fsm;                 // alias over W1s after it is no longer read
    float* qq  = fsm + 8192;
    __shared__ float invs[MR], dgs[MR];

    const int tid = threadIdx.x;
    const int row0 = blockIdx.x * MR;

    {
        const float4* w1 = (const float4*)W1;
        const float4* w2 = (const float4*)W2;
        const float4* xg = (const float4*)(x + (size_t)row0 * D);
#pragma unroll
        for (int it = 0; it < 16; it++) ((float4*)W1s)[it * 256 + tid] = w1[it * 256 + tid];
#pragma unroll
        for (int it = 0; it < 16; it++) ((float4*)W2s)[it * 256 + tid] = w2[it * 256 + tid];
#pragma unroll
        for (int it = 0; it < 8; it++) ((float4*)xs)[it * 256 + tid] = xg[it * 256 + tid];
    }
    __syncthreads();

    // Phase B: hidden = relu(x @ W1 + b1). 512 (r,jg) tasks, 2 per thread.
#pragma unroll
    for (int t2 = 0; t2 < 2; t2++) {
        const int task = t2 * 256 + tid;
        const int r = task >> 4;
        const int jg = task & 15;
        float acc0 = 0.f, acc1 = 0.f, acc2 = 0.f, acc3 = 0.f;
        for (int kk = 0; kk < D; kk += 4) {
            const float4 xv = *(const float4*)&xs[r * D + kk];
            const float4 w0 = *(const float4*)&W1s[(kk + 0) * H + jg * 4];
            const float4 w1v = *(const float4*)&W1s[(kk + 1) * H + jg * 4];
            const float4 w2v = *(const float4*)&W1s[(kk + 2) * H + jg * 4];
            const float4 w3 = *(const float4*)&W1s[(kk + 3) * H + jg * 4];
            acc0 = fmaf(xv.x, w0.x, acc0); acc1 = fmaf(xv.x, w0.y, acc1);
            acc2 = fmaf(xv.x, w0.z, acc2); acc3 = fmaf(xv.x, w0.w, acc3);
            acc0 = fmaf(xv.y, w1v.x, acc0); acc1 = fmaf(xv.y, w1v.y, acc1);
            acc2 = fmaf(xv.y, w1v.z, acc2); acc3 = fmaf(xv.y, w1v.w, acc3);
            acc0 = fmaf(xv.z, w2v.x, acc0); acc1 = fmaf(xv.z, w2v.y, acc1);
            acc2 = fmaf(xv.z, w2v.z, acc2); acc3 = fmaf(xv.z, w2v.w, acc3);
            acc0 = fmaf(xv.w, w3.x, acc0); acc1 = fmaf(xv.w, w3.y, acc1);
            acc2 = fmaf(xv.w, w3.z, acc2); acc3 = fmaf(xv.w, w3.w, acc3);
        }
        hs[r * H + jg * 4 + 0] = fmaxf(acc0 + b1[jg * 4 + 0], 0.f);
        hs[r * H + jg * 4 + 1] = fmaxf(acc1 + b1[jg * 4 + 1], 0.f);
        hs[r * H + jg * 4 + 2] = fmaxf(acc2 + b1[jg * 4 + 2], 0.f);
        hs[r * H + jg * 4 + 3] = fmaxf(acc3 + b1[jg * 4 + 3], 0.f);
    }
    __syncthreads();

    // Phase C: pred col c = tid across 32 rows.
    const int c = tid;
    float p[MR];
    {
        const float bb = b2[c];
#pragma unroll
        for (int r = 0; r < MR; r++) p[r] = bb;
        for (int jq = 0; jq < 16; jq++) {
            const float w0 = W2s[(jq * 4 + 0) * D + c];
            const float w1v = W2s[(jq * 4 + 1) * D + c];
            const float w2v = W2s[(jq * 4 + 2) * D + c];
            const float w3 = W2s[(jq * 4 + 3) * D + c];
#pragma unroll
            for (int r = 0; r < MR; r++) {
                const float4 h4 = *(const float4*)&hs[r * H + jq * 4];
                p[r] = fmaf(h4.x, w0, p[r]);
                p[r] = fmaf(h4.y, w1v, p[r]);
                p[r] = fmaf(h4.z, w2v, p[r]);
                p[r] = fmaf(h4.w, w3, p[r]);
            }
        }
    }
    __syncthreads();   // everyone done reading W1s before ss/qq alias writes
#pragma unroll
    for (int r = 0; r < MR; r++) {
        ss[r * D + c] = p[r] * p[r];
        qq[r * D + c] = p[r] * g_tn32[(size_t)(row0 + r) * D + c];
    }
    __syncthreads();

    // row reductions: warp w handles rows w*4 .. w*4+3
    {
        const int wid = tid >> 5, lane = tid & 31;
#pragma unroll
        for (int m = 0; m < 4; m++) {
            const int r = wid * 4 + m;
            float s1 = 0.f, s2 = 0.f;
#pragma unroll
            for (int s = 0; s < 8; s++) {
                s1 += ss[r * D + lane + 32 * s];
                s2 += qq[r * D + lane + 32 * s];
            }
#pragma unroll
            for (int o = 16; o > 0; o >>= 1) {
                s1 += __shfl_xor_sync(0xFFFFFFFF, s1, o);
                s2 += __shfl_xor_sync(0xFFFFFFFF, s2, o);
            }
            if (lane == 0) {
                invs[r] = 1.0f / fmaxf(sqrtf(s1), 1e-12f);
                dgs[r] = s2;
            }
        }
    }
    __syncthreads();

#pragma unroll
    for (int r = 0; r < MR; r++)
        g_pnb[(size_t)(row0 + r) * D + c] = __float2bfloat16(p[r] * invs[r]);
    if (tid < MR) g_diag[row0 + tid] = dgs[tid] * invs[tid];
}

// ---------------------------------------------------------------------------
// Kernel 3: bf16 mma.sync GEMM + fused per-row top-10 (largest dot) selection.
// Grid 128 = 64 row-blocks x 2 column halves. 256 threads (2x4 warp grid).
// Warp tile 64x32, atoms m16n8k16. A/B staged in padded SMEM, ldmatrix loads.
// ---------------------------------------------------------------------------
#define BM 128
#define BN 128
#define SSTR 264      // halfs per smem row (528 B, 16B-aligned, conflict-free)
#define CSTR 132      // floats per C smem row

extern __shared__ char dsm[];
__global__ __launch_bounds__(256) void gemm_topk_kernel() {
    const int tid = threadIdx.x;
    const int wid = tid >> 5, lane = tid & 31;
    const int wr = wid >> 2, wc = wid & 3;       // 2 x 4 warps
    const int bx = blockIdx.x;
    const int row0 = (bx >> 1) * BM;
    const int half = bx & 1;
    const int cbeg = half * 4096;

    __nv_bfloat16* As = (__nv_bfloat16*)dsm;                 // 128*264*2 = 67584 B
    __nv_bfloat16* Bs = (__nv_bfloat16*)(dsm + 67584);       // 67584 B
    float*         Cs = (float*)(dsm + 135168);              // 128*132*4 = 67584 B
    const uint32_t As_a = smem_u32(As);
    const uint32_t Bs_a = smem_u32(Bs);

    // Load A tile once: 128 rows x 256 bf16 (each thread 16 x uint4)
    {
        const uint4* src = (const uint4*)(g_pnb + (size_t)row0 * D);
#pragma unroll
        for (int it = 0; it < 16; it++) {
            const int lin = it * 256 + tid;      // 0..4095
            const int r = lin >> 5, c16 = lin & 31;
            *(uint4*)(As + r * SSTR + c16 * 8) = src[lin];
        }
    }

    // ldmatrix per-lane address components
    const int a_row_off = (lane & 7) + ((lane >> 3) & 1) * 8;
    const int a_k_off   = (lane >> 4) * 8;
    const int b_col_off = (lane & 7) + ((lane >> 4) & 1) * 8;
    const int b_k_off   = ((lane >> 3) & 1) * 8;

    uint32_t a_base[4], b_base[2];
#pragma unroll
    for (int mi = 0; mi < 4; mi++)
        a_base[mi] = As_a + ((wr * 64 + mi * 16 + a_row_off) * SSTR + a_k_off) * 2;
#pragma unroll
    for (int nb = 0; nb < 2; nb++)
        b_base[nb] = Bs_a + ((wc * 32 + nb * 16 + b_col_off) * SSTR + b_k_off) * 2;

    // scan assignment: thread owns (row = tid&127, 64-col half = tid>>7)
    const int srow = tid & 127;
    const int shalf = tid >> 7;
    const int my_row = row0 + srow;
    float top[10];
#pragma unroll
    for (int q = 0; q < 10; q++) top[q] = -1e30f;

    for (int t = 0; t < 32; t++) {
        const int c0 = cbeg + t * BN;
        // Load B tile: 128 targets x 256 bf16
        {
            const uint4* src = (const uint4*)(g_tnb + (size_t)c0 * D);
#pragma unroll
            for (int it = 0; it < 16; it++) {
                const int lin = it * 256 + tid;
                const int r = lin >> 5, c16 = lin & 31;
                *(uint4*)(Bs + r * SSTR + c16 * 8) = src[lin];
            }
        }
        __syncthreads();   // B visible; also orders prev scan before C overwrite

        float acc[4][4][4];
#pragma unroll
        for (int mi = 0; mi < 4; mi++)
#pragma unroll
            for (int ni = 0; ni < 4; ni++)
#pragma unroll
                for (int q = 0; q < 4; q++) acc[mi][ni][q] = 0.f;

#pragma unroll
        for (int ks = 0; ks < 16; ks++) {
            uint32_t a[4][4], b[4][2];
#pragma unroll
            for (int mi = 0; mi < 4; mi++)
                ldmatrix_x4(a[mi][0], a[mi][1], a[mi][2], a[mi][3], a_base[mi] + ks * 32);
#pragma unroll
            for (int nb = 0; nb < 2; nb++) {
                uint32_t r0, r1, r2, r3;
                ldmatrix_x4(r0, r1, r2, r3, b_base[nb] + ks * 32);
                b[nb * 2 + 0][0] = r0; b[nb * 2 + 0][1] = r1;
                b[nb * 2 + 1][0] = r2; b[nb * 2 + 1][1] = r3;
            }
#pragma unroll
            for (int mi = 0; mi < 4; mi++)
#pragma unroll
                for (int ni = 0; ni < 4; ni++)
                    mma_bf16(acc[mi][ni], a[mi], b[ni]);
        }

        // Write C tile to SMEM
        {
            const int r0l = wr * 64 + (lane >> 2);
            const int c0l = wc * 32 + (lane & 3) * 2;
#pragma unroll
            for (int mi = 0; mi < 4; mi++)
#pragma unroll
                for (int ni = 0; ni < 4; ni++) {
                    float* p0 = Cs + (r0l + mi * 16) * CSTR + c0l + ni * 8;
                    p0[0] = acc[mi][ni][0]; p0[1] = acc[mi][ni][1];
                    float* p1 = p0 + 8 * CSTR;
                    p1[0] = acc[mi][ni][2]; p1[1] = acc[mi][ni][3];
                }
        }
        __syncthreads();

        // Scan: each thread scans 64 cols of its row, staggered start
        {
            const float* rowp = Cs + srow * CSTR + shalf * 64;
            const int jb = c0 + shalf * 64;
#pragma unroll 4
            for (int i = 0; i < 64; i++) {
                const int cl = (srow + i) & 63;
                const float v = rowp[cl];
                if (v > top[9] && (jb + cl) != my_row) {
                    top[9] = v;
#pragma unroll
                    for (int pq = 9; pq > 0; pq--) {
                        if (top[pq] > top[pq - 1]) {
                            const float tmp = top[pq - 1];
                            top[pq - 1] = top[pq];
                            top[pq] = tmp;
                        }
                    }
                }
            }
        }
        // next iteration's post-B-load __syncthreads orders scan before C overwrite
    }

    // Merge the two per-row 64-col lists via Cs scratch
    __syncthreads();
    float* lists = Cs;                      // 256 * 10 floats
#pragma unroll
    for (int q = 0; q < 10; q++) lists[tid * 10 + q] = top[q];
    __syncthreads();
    if (tid < 128) {
        const float* la = lists + tid * 10;
        const float* lb = lists + (tid + 128) * 10;
        float out[10];
        int ia = 0, ib = 0;
#pragma unroll
        for (int q = 0; q < 10; q++) {
            const float va = la[ia], vb = lb[ib];
            if (va >= vb) { out[q] = va; ia++; }
            else          { out[q] = vb; ib++; }
        }
        float* dst = g_part + ((size_t)half * N + row0 + tid) * 10;
#pragma unroll
        for (int q = 0; q < 10; q++) dst[q] = out[q];
    }
}

// ---------------------------------------------------------------------------
// Kernel 4: merge per-half top-10 lists, form per-row loss term.
// ---------------------------------------------------------------------------
__global__ void terms_kernel() {
    const int i = blockIdx.x * blockDim.x + threadIdx.x;
    const float* a = g_part + (size_t)i * 10;
    const float* b = g_part + ((size_t)N + i) * 10;
    int ia = 0, ib = 0;
    float s9 = 0.0f;
#pragma unroll
    for (int r = 0; r < 10; r++) {
        float v;
        if (ib >= 10 || (ia < 10 && a[ia] >= b[ib])) v = a[ia++];
        else v = b[ib++];
        if (r > 0) s9 += v;
    }
    const float dist_an = (-2.0f / 9.0f) * s9;
    const float dist_ap = -2.0f * g_diag[i];
    g_terms[i] = fmaxf(0.0f, GAMMA * dist_ap - dist_an + MARGIN);
}

// ---------------------------------------------------------------------------
// Kernel 5: deterministic fixed-order mean reduction.
// ---------------------------------------------------------------------------
__global__ void reduce_kernel(float* __restrict__ out) {
    __shared__ float red[256];
    const int t = threadIdx.x;
    float s = 0.0f;
    for (int i = t; i < N; i += 256) s += g_terms[i];
    red[t] = s;
    __syncthreads();
#pragma unroll
    for (int sft = 128; sft > 0; sft >>= 1) {
        if (t < sft) red[t] += red[t + sft];
        __syncthreads();
    }
    if (t == 0) out[0] = red[0] / (float)N;
}

// ---------------------------------------------------------------------------
extern "C" void kernel_launch(void* const* d_in, const int* in_sizes, int n_in,
                              void* d_out, int out_size) {
    const float* input  = (const float*)d_in[0];
    const float* target = (const float*)d_in[1];
    const float* W1     = (const float*)d_in[2];
    const float* b1     = (const float*)d_in[3];
    const float* W2     = (const float*)d_in[4];
    const float* b2     = (const float*)d_in[5];
    float* out = (float*)d_out;

    cudaFuncSetAttribute(mlp_kernel, cudaFuncAttributeMaxDynamicSharedMemorySize, 172032);
    cudaFuncSetAttribute(gemm_topk_kernel, cudaFuncAttributeMaxDynamicSharedMemorySize, 202752);

    target_norm_kernel<<<N, 256>>>(target);
    mlp_kernel<<<N / MR, 256, 172032>>>(input, W1, b1, W2, b2);
    gemm_topk_kernel<<<128, 256, 202752>>>();
    terms_kernel<<<N / 256, 256>>>();
    reduce_kernel<<<1, 256>>>(out);
}